// round 16
// baseline (speedup 1.0000x reference)
#include <cuda_runtime.h>
#include <cuda_fp16.h>
#include <cstdint>

#define MULV    128
#define NZ_COLS 512
#define PW_SS 0.0625f
#define PW_VV 0.03608439182435161f
#define PW_SV 0.0078125f

// Packed weights (fp16): g_wp[v][w][u] (4.2 MB), g_wss[u][v], g_wvv[u][v]
__device__ unsigned char g_wp[128u * 128u * 256u];
__device__ unsigned char g_wss[128u * 256u];
__device__ unsigned char g_wvv[128u * 256u];

// ---------------- helpers ----------------
__device__ __forceinline__ uint32_t smem_u32(const void* p) {
    uint32_t a;
    asm("{ .reg .u64 t; cvta.to.shared.u64 t, %1; cvt.u32.u64 %0, t; }" : "=r"(a) : "l"(p));
    return a;
}
__device__ __forceinline__ void ldsm4(uint32_t r[4], uint32_t addr) {
    asm volatile("ldmatrix.sync.aligned.m8n8.x4.shared.b16 {%0,%1,%2,%3}, [%4];"
                 : "=r"(r[0]), "=r"(r[1]), "=r"(r[2]), "=r"(r[3]) : "r"(addr));
}
__device__ __forceinline__ void mma_f16(float c[4], const uint32_t a[4],
                                        uint32_t b0, uint32_t b1) {
    asm volatile("mma.sync.aligned.m16n8k16.row.col.f32.f16.f16.f32 "
                 "{%0,%1,%2,%3}, {%4,%5,%6,%7}, {%8,%9}, {%0,%1,%2,%3};"
                 : "+f"(c[0]), "+f"(c[1]), "+f"(c[2]), "+f"(c[3])
                 : "r"(a[0]), "r"(a[1]), "r"(a[2]), "r"(a[3]), "r"(b0), "r"(b1));
}
__device__ __forceinline__ void cp16(uint32_t sdst, const void* gsrc) {
    asm volatile("cp.async.cg.shared.global [%0], [%1], 16;" :: "r"(sdst), "l"(gsrc));
}
__device__ __forceinline__ void cp_commit() { asm volatile("cp.async.commit_group;"); }
template <int N> __device__ __forceinline__ void cp_wait() {
    asm volatile("cp.async.wait_group %0;" :: "n"(N));
}
__device__ __forceinline__ uint32_t pack_h2(float f0, float f1) {
    __half h0 = __float2half_rn(f0), h1 = __float2half_rn(f1);
    return (uint32_t)__half_as_ushort(h0) | ((uint32_t)__half_as_ushort(h1) << 16);
}

// ---------------------------------------------------------------------------
// Pack: blocks 0-127: w_sv[u][v][w] -> g_wp[v][w][u] fp16.
//       block 128: w_ss -> g_wss. block 129: w_vv -> g_wvv.
// ---------------------------------------------------------------------------
__global__ void pack_b_kernel(const float* __restrict__ wsv,
                              const float* __restrict__ wss,
                              const float* __restrict__ wvv) {
    extern __shared__ float tile[];              // [128 w][133]
    const int tid = threadIdx.x;
    if (blockIdx.x >= 128) {
        const float* src = (blockIdx.x == 128) ? wss : wvv;
        uint32_t* dst = (uint32_t*)((blockIdx.x == 128) ? g_wss : g_wvv);
        for (int j = tid; j < 8192; j += 256)
            dst[j] = pack_h2(src[2 * j], src[2 * j + 1]);
        return;
    }
    const int v = blockIdx.x;
    for (int idx = tid; idx < 16384; idx += 256) {
        const int u = idx >> 7, w = idx & 127;
        tile[w * 133 + u] = wsv[(size_t)u * 16384 + (size_t)v * 128 + w];
    }
    __syncthreads();
    for (int j = tid; j < 8192; j += 256) {
        const int w = j >> 6, u0 = (j & 63) * 2;
        uint32_t* dst = (uint32_t*)(g_wp + ((size_t)v * 128 + w) * 256);
        dst[u0 >> 1] = pack_h2(tile[w * 133 + u0], tile[w * 133 + u0 + 1]);
    }
}

// ---------------------------------------------------------------------------
// Fused kernel: grid (64 z-tiles, 2 halves), 256 threads (8 warps, m32n32).
// A (xs) fragments in registers (areg, loaded once). v processed in PAIRS:
// one cp_wait+__syncthreads+commit per pair; two sequential single-v GEMMs
// (accumulator c reused, no extra registers). Epilogue reads xv as __half2
// covering (v0,v1): 12 LDS per v-epilogue over 4 distinct rows.
// SMEM: A_xs @0, A_xv0/1/2 @34816/69632/104448 (128x272B each),
//       B ring 4 x 17408B @139264. Total 208896.
// ---------------------------------------------------------------------------
#define A_XV(i)  (34816u * (1u + (i)))
#define B_RING   139264u
#define B_SLOT(v) (B_RING + (uint32_t)((v) & 3) * 17408u)
#define SMEM_MAIN 208896

__global__ __launch_bounds__(256, 1) void sv_mma_kernel(
    const float* __restrict__ x, float* __restrict__ out)
{
    extern __shared__ unsigned char smem[];
    const uint32_t sbase = smem_u32(smem);

    const int tid = threadIdx.x;
    const int lane = tid & 31;
    const int warp = tid >> 5;
    const int m0 = (warp >> 1) * 32;
    const int n0 = (warp & 1) * 32;
    const int z0 = blockIdx.x * 128;
    const int wbase = blockIdx.y * 64;   // w-half AND u-half

    // ---- A_xs tile: fp16, stride 272B ----
    {
        const int row = tid >> 1, uh = (tid & 1) * 64;
        const float4* src = (const float4*)(x + (size_t)(z0 + row) * NZ_COLS + uh);
        uint32_t* dst = (uint32_t*)(smem + row * 272u + uh * 2u);
#pragma unroll
        for (int j = 0; j < 16; ++j) {
            float4 f = src[j];
            dst[2 * j]     = pack_h2(f.x, f.y);
            dst[2 * j + 1] = pack_h2(f.z, f.w);
        }
    }
    // ---- A_xv tiles: de-interleave xv components into 3 fp16 tiles ----
    {
        const int row = tid >> 1;
        const int c0 = (tid & 1) * 192;
        const float4* src = (const float4*)(x + (size_t)(z0 + row) * NZ_COLS + MULV + c0);
#pragma unroll 8
        for (int j = 0; j < 48; ++j) {
            float4 f = src[j];
            float vals[4] = {f.x, f.y, f.z, f.w};
#pragma unroll
            for (int t = 0; t < 4; ++t) {
                int cc = c0 + 4 * j + t;
                int v = cc / 3, i = cc - 3 * v;
                *(__half*)(smem + A_XV(i) + row * 272u + v * 2u) = __float2half_rn(vals[t]);
            }
        }
    }

    const uint32_t aoff = ((lane & 7) + ((lane >> 3) & 1) * 8) * 272u + ((lane >> 4) & 1) * 16u;
    const uint32_t boff = ((lane & 7) + ((lane >> 4) & 1) * 8) * 272u + ((lane >> 3) & 1) * 16u;

// copy one 16KB B tile (64 rows x 256B) into a ring slot: 4 cp16/thread (NO commit)
#define PREFETCH_NC(gsrc, bufaddr) do { \
    const unsigned char* _g = (gsrc); \
    _Pragma("unroll") \
    for (int i = 0; i < 4; ++i) { \
        int c = tid + 256 * i; \
        int r = c >> 4, ch = c & 15; \
        cp16((bufaddr) + (uint32_t)r * 272u + (uint32_t)ch * 16u, \
             _g + (size_t)r * 256 + ch * 16); \
    } \
} while (0)

    // prefetch pair 0 (v=0,1) as one group
    PREFETCH_NC(g_wp + (size_t)wbase * 256, sbase + B_SLOT(0));
    PREFETCH_NC(g_wp + ((size_t)128 + wbase) * 256, sbase + B_SLOT(1));
    cp_commit();

    __syncthreads();     // A tiles visible

    // ---- load ALL A fragments into registers (v-invariant) ----
    uint32_t areg[2][8][4];
    {
        const uint32_t aH0 = sbase + (uint32_t)m0 * 272u + aoff;
        const uint32_t aH1 = sbase + (uint32_t)(m0 + 16) * 272u + aoff;
#pragma unroll
        for (int ks = 0; ks < 8; ++ks) {
            ldsm4(areg[0][ks], aH0 + (uint32_t)ks * 32u);
            ldsm4(areg[1][ks], aH1 + (uint32_t)ks * 32u);
        }
    }

    float o[3][2][4][4];                 // out_v accumulators (persistent)
#pragma unroll
    for (int mi = 0; mi < 2; ++mi)
#pragma unroll
        for (int nf = 0; nf < 4; ++nf)
#pragma unroll
            for (int e = 0; e < 4; ++e) {
                o[0][mi][nf][e] = 0.f; o[1][mi][nf][e] = 0.f; o[2][mi][nf][e] = 0.f;
            }

    const int R0 = m0 + (lane >> 2);

// one single-v GEMM (A from registers) into c
#define GEMM_V(cacc, bu) do { \
    const uint32_t _bN0 = (bu) + (uint32_t)n0 * 272u + boff; \
    const uint32_t _bN1 = (bu) + (uint32_t)(n0 + 16) * 272u + boff; \
    _Pragma("unroll") \
    for (int ks = 0; ks < 8; ++ks) { \
        const uint32_t ko = (uint32_t)ks * 32u; \
        uint32_t b0[4], b1[4]; \
        ldsm4(b0, _bN0 + ko); \
        ldsm4(b1, _bN1 + ko); \
        mma_f16((cacc)[0][0], areg[0][ks], b0[0], b0[1]); \
        mma_f16((cacc)[0][1], areg[0][ks], b0[2], b0[3]); \
        mma_f16((cacc)[0][2], areg[0][ks], b1[0], b1[1]); \
        mma_f16((cacc)[0][3], areg[0][ks], b1[2], b1[3]); \
        mma_f16((cacc)[1][0], areg[1][ks], b0[0], b0[1]); \
        mma_f16((cacc)[1][1], areg[1][ks], b0[2], b0[3]); \
        mma_f16((cacc)[1][2], areg[1][ks], b1[0], b1[1]); \
        mma_f16((cacc)[1][3], areg[1][ks], b1[2], b1[3]); \
    } \
} while (0)

// epilogue for one v of a pair: HI=0 -> low half (v0), HI=1 -> high half (v1).
// 12 LDS (4 rows x 3 comps) per call; 96 FFMA.
#define EPILOGUE_V(cacc, v0, HI) do { \
    _Pragma("unroll") \
    for (int rj = 0; rj < 4; ++rj) { \
        const int mi = rj >> 1; \
        const uint32_t roff = (uint32_t)(R0 + 8 * rj) * 272u + (uint32_t)(v0) * 2u; \
        __half2 h0 = *(const __half2*)(smem + A_XV(0) + roff); \
        __half2 h1 = *(const __half2*)(smem + A_XV(1) + roff); \
        __half2 h2 = *(const __half2*)(smem + A_XV(2) + roff); \
        const float x0 = (HI) ? __high2float(h0) : __low2float(h0); \
        const float x1 = (HI) ? __high2float(h1) : __low2float(h1); \
        const float x2 = (HI) ? __high2float(h2) : __low2float(h2); \
        _Pragma("unroll") \
        for (int e2 = 0; e2 < 2; ++e2) { \
            const int e = (rj & 1) * 2 + e2; \
            _Pragma("unroll") \
            for (int nf = 0; nf < 4; ++nf) { \
                const float t = (cacc)[mi][nf][e]; \
                o[0][mi][nf][e] += t * x0; \
                o[1][mi][nf][e] += t * x1; \
                o[2][mi][nf][e] += t * x2; \
            } \
        } \
    } \
} while (0)

    // =================== paired v-loop ===================
    for (int p = 0; p < 64; ++p) {
        const int v0 = 2 * p;
        cp_wait<0>();                    // tiles for this pair resident
        __syncthreads();                 // all warps done with the other 2 slots
        if (p < 63) {
            PREFETCH_NC(g_wp + ((size_t)(v0 + 2) * 128 + wbase) * 256, sbase + B_SLOT(v0 + 2));
            PREFETCH_NC(g_wp + ((size_t)(v0 + 3) * 128 + wbase) * 256, sbase + B_SLOT(v0 + 3));
        } else {
            PREFETCH_NC(g_wss + (size_t)wbase * 256, sbase + B_SLOT(0));
            PREFETCH_NC(g_wvv + (size_t)wbase * 256, sbase + B_SLOT(1));
        }
        cp_commit();

        float c[2][4][4];
        // ---- v0 ----
#pragma unroll
        for (int mi = 0; mi < 2; ++mi)
#pragma unroll
            for (int nf = 0; nf < 4; ++nf)
#pragma unroll
                for (int e = 0; e < 4; ++e) c[mi][nf][e] = 0.f;
        GEMM_V(c, sbase + B_SLOT(v0));
        EPILOGUE_V(c, v0, 0);
        // ---- v1 ----
#pragma unroll
        for (int mi = 0; mi < 2; ++mi)
#pragma unroll
            for (int nf = 0; nf < 4; ++nf)
#pragma unroll
                for (int e = 0; e < 4; ++e) c[mi][nf][e] = 0.f;
        GEMM_V(c, sbase + B_SLOT(v0 + 1));
        EPILOGUE_V(c, v0, 1);
    }

    // =================== peeled tail: ss + vv terms ===================
    {
        float o2[2][4][4];

        cp_wait<0>();
        __syncthreads();
        // ---- ss: B = g_wss (slot 0); A from registers
        {
            float c[2][4][4];
#pragma unroll
            for (int mi = 0; mi < 2; ++mi)
#pragma unroll
                for (int nf = 0; nf < 4; ++nf)
#pragma unroll
                    for (int e = 0; e < 4; ++e) c[mi][nf][e] = 0.f;
            GEMM_V(c, sbase + B_SLOT(0));
#pragma unroll
            for (int mi = 0; mi < 2; ++mi)
#pragma unroll
                for (int e = 0; e < 4; ++e) {
                    const int row = z0 + R0 + 16 * mi + 8 * (e >> 1);
#pragma unroll
                    for (int nf = 0; nf < 4; ++nf) {
                        const int u = wbase + n0 + 8 * nf + (lane & 3) * 2 + (e & 1);
                        o2[mi][nf][e] = PW_SS * __ldg(x + (size_t)row * NZ_COLS + u) * c[mi][nf][e];
                    }
                }
        }

        // ---- vv: 3 GEMMs sharing B = g_wvv (slot 1); A from A_XV smem
        {
            const uint32_t bu = sbase + B_SLOT(1);
            const uint32_t bN0 = bu + (uint32_t)n0 * 272u + boff;
            const uint32_t bN1 = bu + (uint32_t)(n0 + 16) * 272u + boff;
#pragma unroll 1
            for (int i = 0; i < 3; ++i) {
                const uint32_t aV0 = sbase + A_XV(i) + (uint32_t)m0 * 272u + aoff;
                const uint32_t aV1 = sbase + A_XV(i) + (uint32_t)(m0 + 16) * 272u + aoff;
                float c[2][4][4];
#pragma unroll
                for (int mi = 0; mi < 2; ++mi)
#pragma unroll
                    for (int nf = 0; nf < 4; ++nf)
#pragma unroll
                        for (int e = 0; e < 4; ++e) c[mi][nf][e] = 0.f;
#pragma unroll
                for (int ks = 0; ks < 8; ++ks) {
                    const uint32_t ko = (uint32_t)ks * 32u;
                    uint32_t a0[4], a1[4], b0[4], b1[4];
                    ldsm4(a0, aV0 + ko);
                    ldsm4(a1, aV1 + ko);
                    ldsm4(b0, bN0 + ko);
                    ldsm4(b1, bN1 + ko);
                    mma_f16(c[0][0], a0, b0[0], b0[1]);
                    mma_f16(c[0][1], a0, b0[2], b0[3]);
                    mma_f16(c[0][2], a0, b1[0], b1[1]);
                    mma_f16(c[0][3], a0, b1[2], b1[3]);
                    mma_f16(c[1][0], a1, b0[0], b0[1]);
                    mma_f16(c[1][1], a1, b0[2], b0[3]);
                    mma_f16(c[1][2], a1, b1[0], b1[1]);
                    mma_f16(c[1][3], a1, b1[2], b1[3]);
                }
#pragma unroll
                for (int mi = 0; mi < 2; ++mi)
#pragma unroll
                    for (int e = 0; e < 4; ++e) {
                        const int row = z0 + R0 + 16 * mi + 8 * (e >> 1);
#pragma unroll
                        for (int nf = 0; nf < 4; ++nf) {
                            const int u = wbase + n0 + 8 * nf + (lane & 3) * 2 + (e & 1);
                            o2[mi][nf][e] += PW_VV *
                                __ldg(x + (size_t)row * NZ_COLS + MULV + 3 * u + i) * c[mi][nf][e];
                        }
                    }
            }
        }

        // ---- final stores (out_s + out_v) ----
#pragma unroll
        for (int mi = 0; mi < 2; ++mi)
#pragma unroll
            for (int e = 0; e < 4; ++e) {
                const int row = z0 + R0 + 16 * mi + 8 * (e >> 1);
#pragma unroll
                for (int nf = 0; nf < 4; ++nf) {
                    const int w = wbase + n0 + 8 * nf + (lane & 3) * 2 + (e & 1);
                    float* p = out + (size_t)row * NZ_COLS + MULV + 3 * w;
                    p[0] = PW_SV * o[0][mi][nf][e];
                    p[1] = PW_SV * o[1][mi][nf][e];
                    p[2] = PW_SV * o[2][mi][nf][e];
                    out[(size_t)row * NZ_COLS + w] = o2[mi][nf][e];
                }
            }
    }
}

// ---------------------------------------------------------------------------
extern "C" void kernel_launch(void* const* d_in, const int* in_sizes, int n_in,
                              void* d_out, int out_size)
{
    const float* x    = (const float*)d_in[0];
    const float* w_ss = (const float*)d_in[1];
    const float* w_sv = (const float*)d_in[2];
    const float* w_vv = (const float*)d_in[3];
    float* out = (float*)d_out;

    const int n = in_sizes[0] / NZ_COLS;           // 8192
    const int pack_smem = 128 * 133 * 4;           // ~68 KB

    cudaFuncSetAttribute(pack_b_kernel, cudaFuncAttributeMaxDynamicSharedMemorySize, pack_smem);
    cudaFuncSetAttribute(sv_mma_kernel, cudaFuncAttributeMaxDynamicSharedMemorySize, SMEM_MAIN);

    pack_b_kernel<<<130, 256, pack_smem>>>(w_sv, w_ss, w_vv);
    sv_mma_kernel<<<dim3(n / 128, 2), 256, SMEM_MAIN>>>(x, out);
}